// round 12
// baseline (speedup 1.0000x reference)
#include <cuda_runtime.h>
#include <cuda_bf16.h>

// QIntSoftmax: software-pipelined warp-per-row. Each warp processes ITERS rows,
// double-buffered: row k+1's 8x LDG.128 are issued before row k's compute+store,
// so loads overlap the long dependent compute region (2x time-averaged MLP).
// Invariants vs the reference (unchanged since R5, rel_err = 1.276735e-4):
//  - max element maps to xi = 0 exactly (scale each elem, then subtract max)
//  - common power-of-2 rescale (drop 2^30) leaves sum/e bit-identical
//  - division is faithful (<=1 ulp): rcp.approx + 1 Newton step on quotient
//  - rint+log2 bucket logic folded into exponent-field bit trick (u = so+0.5)

constexpr int ROW     = 1024;
constexpr int THREADS = 128;
constexpr int WARPS   = THREADS / 32;   // 4 rows in flight per CTA per iter
constexpr int ITERS   = 16;             // rows per warp
constexpr int V4      = ROW / 32 / 4;   // 8 float4 per lane per row

__device__ __forceinline__ float ex2_approx(float a) {
    float r; asm("ex2.approx.ftz.f32 %0, %1;" : "=f"(r) : "f"(a)); return r;
}
__device__ __forceinline__ float rcp_approx(float a) {
    float r; asm("rcp.approx.ftz.f32 %0, %1;" : "=f"(r) : "f"(a)); return r;
}

struct QConsts { float rs, x0_int, nr_x0, b_int, c_int; };

__device__ __forceinline__ void load_row(float4 (&v)[V4],
                                         const float* __restrict__ base,
                                         int lane)
{
    const float4* __restrict__ in4 = reinterpret_cast<const float4*>(base);
    #pragma unroll
    for (int i = 0; i < V4; i++)
        v[i] = __ldcs(&in4[i * 32 + lane]);
}

__device__ __forceinline__ void process_row(float4 (&v)[V4],
                                            float* __restrict__ obase,
                                            int lane, const QConsts& c)
{
    // ---- max over scaled values ----
    float m = -3.4e38f;
    #pragma unroll
    for (int i = 0; i < V4; i++) {
        float4 t = v[i];
        t.x = __fmul_rn(t.x, c.rs);
        t.y = __fmul_rn(t.y, c.rs);
        t.z = __fmul_rn(t.z, c.rs);
        t.w = __fmul_rn(t.w, c.rs);
        v[i] = t;
        m = fmaxf(m, fmaxf(fmaxf(t.x, t.y), fmaxf(t.z, t.w)));
    }
    #pragma unroll
    for (int off = 16; off; off >>= 1)
        m = fmaxf(m, __shfl_xor_sync(0xFFFFFFFFu, m, off));

    // ---- integer-exp approx (common 2^-30 rescale); accumulate sum ----
    float* vf = reinterpret_cast<float*>(v);
    float sum = 0.0f;
    #pragma unroll
    for (int i = 0; i < 4 * V4; i++) {
        float xi = __fsub_rn(vf[i], m);                 // <= 0, exact 0 at row max
        float qn = ceilf(__fmul_rn(xi, c.nr_x0));       // qn = -q in [-14, 0]
        float r  = __fmaf_rn(c.x0_int, qn, xi);         // exact residual
        float z  = __fmaf_rn(r, r, __fmaf_rn(c.b_int, r, c.c_int)); // > 0
        float ee = __fmul_rn(z, ex2_approx(qn));        // z * 2^-q (exact scaling)
        sum = __fadd_rn(sum, ee);
        vf[i] = ee;
    }
    #pragma unroll
    for (int off = 16; off; off >>= 1)
        sum = __fadd_rn(sum, __shfl_xor_sync(0xFFFFFFFFu, sum, off));

    // ---- log2-round quantization + streaming store ----
    float4* __restrict__ out4 = reinterpret_cast<float4*>(obase);
    #pragma unroll
    for (int i = 0; i < V4; i++) {
        float4 t = v[i];
        float4 o;
        #pragma unroll
        for (int j = 0; j < 4; j++) {
            float e = (j == 0) ? t.x : (j == 1) ? t.y : (j == 2) ? t.z : t.w;
            float y   = rcp_approx(e);
            float so0 = __fmul_rn(sum, y);
            float so  = __fmaf_rn(__fmaf_rn(-e, so0, sum), y, so0);
            unsigned b  = __float_as_uint(__fadd_rn(so, 0.5f));
            unsigned eb = (b + 0x400000u) & 0x7F800000u;
            float oo = __uint_as_float(0x7F000000u - eb);
            if (j == 0) o.x = oo; else if (j == 1) o.y = oo;
            else if (j == 2) o.z = oo; else o.w = oo;
        }
        __stcs(&out4[i * 32 + lane], o);
    }
}

__global__ __launch_bounds__(THREADS)
void qis_main(const float* __restrict__ x,
              const float* __restrict__ scale,
              float* __restrict__ out)
{
    const int lane = threadIdx.x & 31;
    const int wrp  = threadIdx.x >> 5;
    // warp's row for iteration it: ((bid*ITERS + it) * WARPS + wrp)
    const long long base_row = ((long long)blockIdx.x * ITERS) * WARPS + wrp;
    const float* __restrict__ ibase = x   + base_row * ROW;
    float* __restrict__       obase = out + base_row * ROW;
    constexpr long long STEP = (long long)WARPS * ROW;   // row stride per iter

    // ---- prologue: load iter 0, then constants under the load shadow ----
    float4 a[V4], b[V4];
    load_row(a, ibase, lane);

    QConsts c;
    {
        const float s = scale[0];
        c.rs     = __fdiv_rn(1.0f, s);
        c.x0_int = floorf(__fdiv_rn(-0.6931f, s));            // < 0
        c.nr_x0  = -__fdiv_rn(1.0f, c.x0_int);                // > 0
        c.b_int  = floorf(__fdiv_rn((float)(0.96963238 / 0.35815147), s));
        c.c_int  = floorf(__fdiv_rn((float)(1.0 / 0.35815147),
                                    __fmul_rn(s, s)));
    }

    // ---- steady state: prefetch next row, then process current ----
    #pragma unroll
    for (int it = 0; it < ITERS; it += 2) {
        if (it + 1 < ITERS)
            load_row(b, ibase + (it + 1) * STEP, lane);
        process_row(a, obase + it * STEP, lane, c);

        if (it + 2 < ITERS)
            load_row(a, ibase + (it + 2) * STEP, lane);
        if (it + 1 < ITERS)
            process_row(b, obase + (it + 1) * STEP, lane, c);
    }
}

extern "C" void kernel_launch(void* const* d_in, const int* in_sizes, int n_in,
                              void* d_out, int out_size)
{
    int xi = 0, si = 1;
    if (n_in >= 2 && in_sizes[1] > in_sizes[0]) { xi = 1; si = 0; }
    const float* x     = (const float*)d_in[xi];
    const float* scale = (const float*)d_in[si];
    float* out = (float*)d_out;

    int rows = in_sizes[xi] / ROW;               // 98304 for this dataset
    int grid = rows / (WARPS * ITERS);           // 1536
    qis_main<<<grid, THREADS>>>(x, scale, out);
}

// round 13
// speedup vs baseline: 1.3831x; 1.3831x over previous
#include <cuda_runtime.h>
#include <cuda_bf16.h>

// QIntSoftmax: warp-per-row (32 elems/thread, 8x LDG.128 MLP), single kernel.
// __launch_bounds__(256, 5): force <=51 regs so 5 CTAs/SM fit (40 warps vs 32),
// raising time-averaged outstanding loads without cutting per-warp MLP.
// Per-thread constants hidden under the row-load shadow (no smem/barrier).
// Invariants vs the reference (unchanged since R5, rel_err = 1.276735e-4):
//  - max element maps to xi = 0 exactly (scale each elem, then subtract max)
//  - common power-of-2 rescale (drop 2^30) leaves sum/e bit-identical
//  - division is faithful (<=1 ulp): rcp.approx + 1 Newton step on quotient
//  - rint+log2 bucket logic folded into exponent-field bit trick (u = so+0.5)

constexpr int ROW     = 1024;
constexpr int THREADS = 256;
constexpr int RPB     = THREADS / 32;   // 8 rows per CTA
constexpr int V4      = ROW / 32 / 4;   // 8 float4 per lane

__device__ __forceinline__ float ex2_approx(float a) {
    float r; asm("ex2.approx.ftz.f32 %0, %1;" : "=f"(r) : "f"(a)); return r;
}
__device__ __forceinline__ float rcp_approx(float a) {
    float r; asm("rcp.approx.ftz.f32 %0, %1;" : "=f"(r) : "f"(a)); return r;
}

__global__ __launch_bounds__(THREADS, 5)
void qis_main(const float* __restrict__ x,
              const float* __restrict__ scale,
              float* __restrict__ out)
{
    const int lane = threadIdx.x & 31;
    const int wrp  = threadIdx.x >> 5;
    const long long row = (long long)blockIdx.x * RPB + wrp;

    const float4* __restrict__ in4  = reinterpret_cast<const float4*>(x   + row * ROW);
    float4* __restrict__       out4 = reinterpret_cast<float4*>(out + row * ROW);

    // ---- issue all row loads first (max MLP, hides const computation) ----
    float4 v[V4];
    #pragma unroll
    for (int i = 0; i < V4; i++)
        v[i] = __ldcs(&in4[i * 32 + lane]);

    // ---- per-thread constants (exact divisions; latency hidden by loads) ----
    const float s      = scale[0];
    const float rs     = __fdiv_rn(1.0f, s);
    const float x0_int = floorf(__fdiv_rn(-0.6931f, s));              // < 0
    const float nr_x0  = -__fdiv_rn(1.0f, x0_int);                    // > 0
    const float b_int  = floorf(__fdiv_rn((float)(0.96963238 / 0.35815147), s));
    const float c_int  = floorf(__fdiv_rn((float)(1.0 / 0.35815147),
                                          __fmul_rn(s, s)));

    // ---- scale, running max over SCALED values ----
    float m = -3.4e38f;
    #pragma unroll
    for (int i = 0; i < V4; i++) {
        float4 t = v[i];
        t.x = __fmul_rn(t.x, rs);
        t.y = __fmul_rn(t.y, rs);
        t.z = __fmul_rn(t.z, rs);
        t.w = __fmul_rn(t.w, rs);
        v[i] = t;
        m = fmaxf(m, fmaxf(fmaxf(t.x, t.y), fmaxf(t.z, t.w)));
    }
    #pragma unroll
    for (int off = 16; off; off >>= 1)
        m = fmaxf(m, __shfl_xor_sync(0xFFFFFFFFu, m, off));

    // ---- integer-exp approx (common 2^-30 rescale); accumulate sum ----
    float* vf = reinterpret_cast<float*>(v);
    float sum = 0.0f;
    #pragma unroll
    for (int i = 0; i < 4 * V4; i++) {
        float xi = __fsub_rn(vf[i], m);                 // <= 0, exact 0 at row max
        float qn = ceilf(__fmul_rn(xi, nr_x0));         // qn = -q in [-14, 0]
        float r  = __fmaf_rn(x0_int, qn, xi);           // exact residual
        float z  = __fmaf_rn(r, r, __fmaf_rn(b_int, r, c_int));  // >= 3480 > 0
        float ee = __fmul_rn(z, ex2_approx(qn));        // z * 2^-q (exact scaling)
        sum = __fadd_rn(sum, ee);
        vf[i] = ee;
    }
    #pragma unroll
    for (int off = 16; off; off >>= 1)
        sum = __fadd_rn(sum, __shfl_xor_sync(0xFFFFFFFFu, sum, off));

    // ---- log2-round quantization: out = 2^-rounds, streaming store ----
    #pragma unroll
    for (int i = 0; i < V4; i++) {
        float4 t = v[i];
        float4 o;
        #pragma unroll
        for (int j = 0; j < 4; j++) {
            float e = (j == 0) ? t.x : (j == 1) ? t.y : (j == 2) ? t.z : t.w;
            // faithful so = sum/e: approx rcp + 1 Newton step on quotient
            float y   = rcp_approx(e);
            float so0 = __fmul_rn(sum, y);
            float so  = __fmaf_rn(__fmaf_rn(-e, so0, sum), y, so0);
            // u = so + 0.5 puts every bucket boundary exactly at 1.5*2^k:
            // rounds = expfield(u) + (mant(u) >= 0.5); out = 2^-rounds
            unsigned b  = __float_as_uint(__fadd_rn(so, 0.5f));
            unsigned eb = (b + 0x400000u) & 0x7F800000u;
            float oo = __uint_as_float(0x7F000000u - eb);
            if (j == 0) o.x = oo; else if (j == 1) o.y = oo;
            else if (j == 2) o.z = oo; else o.w = oo;
        }
        __stcs(&out4[i * 32 + lane], o);
    }
}

extern "C" void kernel_launch(void* const* d_in, const int* in_sizes, int n_in,
                              void* d_out, int out_size)
{
    int xi = 0, si = 1;
    if (n_in >= 2 && in_sizes[1] > in_sizes[0]) { xi = 1; si = 0; }
    const float* x     = (const float*)d_in[xi];
    const float* scale = (const float*)d_in[si];
    float* out = (float*)d_out;

    int rows = in_sizes[xi] / ROW;
    qis_main<<<rows / RPB, THREADS>>>(x, scale, out);
}

// round 14
// speedup vs baseline: 1.3842x; 1.0008x over previous
#include <cuda_runtime.h>
#include <cuda_bf16.h>

// QIntSoftmax: warp-per-row (32 elems/thread, 8x LDG.128 MLP), single kernel.
// 128-thread CTAs (4 rows) with __launch_bounds__(128, 10): identical per-warp
// datapath and occupancy (40 warps/SM) as the 256-thr config, but half the CTA
// granularity -> half the end-of-kernel drain tail per graph replay.
// Invariants vs the reference (unchanged since R5, rel_err = 1.276735e-4):
//  - max element maps to xi = 0 exactly (scale each elem, then subtract max)
//  - common power-of-2 rescale (drop 2^30) leaves sum/e bit-identical
//  - division is faithful (<=1 ulp): rcp.approx + 1 Newton step on quotient
//  - rint+log2 bucket logic folded into exponent-field bit trick (u = so+0.5)

constexpr int ROW     = 1024;
constexpr int THREADS = 128;
constexpr int RPB     = THREADS / 32;   // 4 rows per CTA
constexpr int V4      = ROW / 32 / 4;   // 8 float4 per lane

__device__ __forceinline__ float ex2_approx(float a) {
    float r; asm("ex2.approx.ftz.f32 %0, %1;" : "=f"(r) : "f"(a)); return r;
}
__device__ __forceinline__ float rcp_approx(float a) {
    float r; asm("rcp.approx.ftz.f32 %0, %1;" : "=f"(r) : "f"(a)); return r;
}

__global__ __launch_bounds__(THREADS, 10)
void qis_main(const float* __restrict__ x,
              const float* __restrict__ scale,
              float* __restrict__ out)
{
    const int lane = threadIdx.x & 31;
    const int wrp  = threadIdx.x >> 5;
    const long long row = (long long)blockIdx.x * RPB + wrp;

    const float4* __restrict__ in4  = reinterpret_cast<const float4*>(x   + row * ROW);
    float4* __restrict__       out4 = reinterpret_cast<float4*>(out + row * ROW);

    // ---- issue all row loads first (max MLP, hides const computation) ----
    float4 v[V4];
    #pragma unroll
    for (int i = 0; i < V4; i++)
        v[i] = __ldcs(&in4[i * 32 + lane]);

    // ---- per-thread constants (exact divisions; latency hidden by loads) ----
    const float s      = scale[0];
    const float rs     = __fdiv_rn(1.0f, s);
    const float x0_int = floorf(__fdiv_rn(-0.6931f, s));              // < 0
    const float nr_x0  = -__fdiv_rn(1.0f, x0_int);                    // > 0
    const float b_int  = floorf(__fdiv_rn((float)(0.96963238 / 0.35815147), s));
    const float c_int  = floorf(__fdiv_rn((float)(1.0 / 0.35815147),
                                          __fmul_rn(s, s)));

    // ---- scale, running max over SCALED values ----
    float m = -3.4e38f;
    #pragma unroll
    for (int i = 0; i < V4; i++) {
        float4 t = v[i];
        t.x = __fmul_rn(t.x, rs);
        t.y = __fmul_rn(t.y, rs);
        t.z = __fmul_rn(t.z, rs);
        t.w = __fmul_rn(t.w, rs);
        v[i] = t;
        m = fmaxf(m, fmaxf(fmaxf(t.x, t.y), fmaxf(t.z, t.w)));
    }
    #pragma unroll
    for (int off = 16; off; off >>= 1)
        m = fmaxf(m, __shfl_xor_sync(0xFFFFFFFFu, m, off));

    // ---- integer-exp approx (common 2^-30 rescale); accumulate sum ----
    float* vf = reinterpret_cast<float*>(v);
    float sum = 0.0f;
    #pragma unroll
    for (int i = 0; i < 4 * V4; i++) {
        float xi = __fsub_rn(vf[i], m);                 // <= 0, exact 0 at row max
        float qn = ceilf(__fmul_rn(xi, nr_x0));         // qn = -q in [-14, 0]
        float r  = __fmaf_rn(x0_int, qn, xi);           // exact residual
        float z  = __fmaf_rn(r, r, __fmaf_rn(b_int, r, c_int));  // >= 3480 > 0
        float ee = __fmul_rn(z, ex2_approx(qn));        // z * 2^-q (exact scaling)
        sum = __fadd_rn(sum, ee);
        vf[i] = ee;
    }
    #pragma unroll
    for (int off = 16; off; off >>= 1)
        sum = __fadd_rn(sum, __shfl_xor_sync(0xFFFFFFFFu, sum, off));

    // ---- log2-round quantization: out = 2^-rounds, streaming store ----
    #pragma unroll
    for (int i = 0; i < V4; i++) {
        float4 t = v[i];
        float4 o;
        #pragma unroll
        for (int j = 0; j < 4; j++) {
            float e = (j == 0) ? t.x : (j == 1) ? t.y : (j == 2) ? t.z : t.w;
            // faithful so = sum/e: approx rcp + 1 Newton step on quotient
            float y   = rcp_approx(e);
            float so0 = __fmul_rn(sum, y);
            float so  = __fmaf_rn(__fmaf_rn(-e, so0, sum), y, so0);
            // u = so + 0.5 puts every bucket boundary exactly at 1.5*2^k:
            // rounds = expfield(u) + (mant(u) >= 0.5); out = 2^-rounds
            unsigned b  = __float_as_uint(__fadd_rn(so, 0.5f));
            unsigned eb = (b + 0x400000u) & 0x7F800000u;
            float oo = __uint_as_float(0x7F000000u - eb);
            if (j == 0) o.x = oo; else if (j == 1) o.y = oo;
            else if (j == 2) o.z = oo; else o.w = oo;
        }
        __stcs(&out4[i * 32 + lane], o);
    }
}

extern "C" void kernel_launch(void* const* d_in, const int* in_sizes, int n_in,
                              void* d_out, int out_size)
{
    int xi = 0, si = 1;
    if (n_in >= 2 && in_sizes[1] > in_sizes[0]) { xi = 1; si = 0; }
    const float* x     = (const float*)d_in[xi];
    const float* scale = (const float*)d_in[si];
    float* out = (float*)d_out;

    int rows = in_sizes[xi] / ROW;
    qis_main<<<rows / RPB, THREADS>>>(x, scale, out);
}

// round 15
// speedup vs baseline: 1.3900x; 1.0042x over previous
#include <cuda_runtime.h>
#include <cuda_bf16.h>

// QIntSoftmax — reproducibility re-bench of the R6 configuration (wall-best
// 121.6us): warp-per-row, smem per-CTA constants, __ldcs/__stcs hints.
// Invariants vs the reference (rel_err = 1.276735e-4 exactly):
//  - max element maps to xi = 0 exactly (scale each elem, then subtract max)
//  - common power-of-2 rescale (drop 2^30) leaves sum/e bit-identical
//  - division is faithful (<=1 ulp): rcp.approx + 1 Newton step on quotient
//  - rint+log2 bucket logic folded into exponent-field bit trick (u = so+0.5)

constexpr int ROW     = 1024;
constexpr int THREADS = 256;
constexpr int RPB     = THREADS / 32;   // 8 rows per CTA
constexpr int V4      = ROW / 32 / 4;   // 8 float4 per lane

__device__ __forceinline__ float ex2_approx(float a) {
    float r; asm("ex2.approx.ftz.f32 %0, %1;" : "=f"(r) : "f"(a)); return r;
}
__device__ __forceinline__ float rcp_approx(float a) {
    float r; asm("rcp.approx.ftz.f32 %0, %1;" : "=f"(r) : "f"(a)); return r;
}

__global__ __launch_bounds__(THREADS)
void qis_main(const float* __restrict__ x,
              const float* __restrict__ scale,
              float* __restrict__ out)
{
    // ---- per-CTA uniform constants (exact divisions, thread 0 only) ----
    __shared__ __align__(16) float cs[8];
    if (threadIdx.x == 0) {
        float s = scale[0];
        float x0i = floorf(__fdiv_rn(-0.6931f, s));
        cs[0] = __fdiv_rn(1.0f, s);                   // rs = 1/s
        cs[1] = x0i;                                  // x0_int < 0
        cs[2] = -__fdiv_rn(1.0f, x0i);                // -1/x0_int > 0
        cs[3] = floorf(__fdiv_rn((float)(0.96963238 / 0.35815147), s));        // b_int
        cs[4] = floorf(__fdiv_rn((float)(1.0 / 0.35815147), __fmul_rn(s, s))); // c_int
    }
    __syncthreads();
    const float4 c4    = reinterpret_cast<const float4*>(cs)[0];
    const float rs     = c4.x;
    const float x0_int = c4.y;
    const float nr_x0  = c4.z;
    const float b_int  = c4.w;
    const float c_int  = cs[4];

    const int lane = threadIdx.x & 31;
    const int wrp  = threadIdx.x >> 5;
    const long long row = (long long)blockIdx.x * RPB + wrp;

    const float4* __restrict__ in4  = reinterpret_cast<const float4*>(x   + row * ROW);
    float4* __restrict__       out4 = reinterpret_cast<float4*>(out + row * ROW);

    // ---- streaming load, scale, running max over SCALED values ----
    float4 v[V4];
    float m = -3.4e38f;
    #pragma unroll
    for (int i = 0; i < V4; i++) {
        float4 t = __ldcs(&in4[i * 32 + lane]);       // evict-first: read-once data
        t.x = __fmul_rn(t.x, rs);
        t.y = __fmul_rn(t.y, rs);
        t.z = __fmul_rn(t.z, rs);
        t.w = __fmul_rn(t.w, rs);
        v[i] = t;
        m = fmaxf(m, fmaxf(fmaxf(t.x, t.y), fmaxf(t.z, t.w)));
    }
    #pragma unroll
    for (int off = 16; off; off >>= 1)
        m = fmaxf(m, __shfl_xor_sync(0xFFFFFFFFu, m, off));

    // ---- integer-exp approx (common 2^-30 rescale); accumulate sum ----
    float* vf = reinterpret_cast<float*>(v);
    float sum = 0.0f;
    #pragma unroll
    for (int i = 0; i < 4 * V4; i++) {
        float xi = __fsub_rn(vf[i], m);                 // <= 0, exact 0 at row max
        float qn = ceilf(__fmul_rn(xi, nr_x0));         // qn = -q in [-14, 0]
        float r  = __fmaf_rn(x0_int, qn, xi);           // exact residual
        float z  = __fmaf_rn(r, r, __fmaf_rn(b_int, r, c_int));  // >= 3480 > 0
        float ee = __fmul_rn(z, ex2_approx(qn));        // z * 2^-q (exact scaling)
        sum = __fadd_rn(sum, ee);
        vf[i] = ee;
    }
    #pragma unroll
    for (int off = 16; off; off >>= 1)
        sum = __fadd_rn(sum, __shfl_xor_sync(0xFFFFFFFFu, sum, off));

    // ---- log2-round quantization: out = 2^-rounds, streaming store ----
    #pragma unroll
    for (int i = 0; i < V4; i++) {
        float4 t = v[i];
        float4 o;
        #pragma unroll
        for (int j = 0; j < 4; j++) {
            float e = (j == 0) ? t.x : (j == 1) ? t.y : (j == 2) ? t.z : t.w;
            // faithful so = sum/e: approx rcp + 1 Newton step on quotient
            float y   = rcp_approx(e);
            float so0 = __fmul_rn(sum, y);
            float so  = __fmaf_rn(__fmaf_rn(-e, so0, sum), y, so0);
            // u = so + 0.5 puts every bucket boundary exactly at 1.5*2^k:
            // rounds = expfield(u) + (mant(u) >= 0.5); out = 2^-rounds
            unsigned b  = __float_as_uint(__fadd_rn(so, 0.5f));
            unsigned eb = (b + 0x400000u) & 0x7F800000u;
            float oo = __uint_as_float(0x7F000000u - eb);
            if (j == 0) o.x = oo; else if (j == 1) o.y = oo;
            else if (j == 2) o.z = oo; else o.w = oo;
        }
        __stcs(&out4[i * 32 + lane], o);                // streaming store
    }
}

extern "C" void kernel_launch(void* const* d_in, const int* in_sizes, int n_in,
                              void* d_out, int out_size)
{
    int xi = 0, si = 1;
    if (n_in >= 2 && in_sizes[1] > in_sizes[0]) { xi = 1; si = 0; }
    const float* x     = (const float*)d_in[xi];
    const float* scale = (const float*)d_in[si];
    float* out = (float*)d_out;

    int rows = in_sizes[xi] / ROW;
    qis_main<<<rows / RPB, THREADS>>>(x, scale, out);
}